// round 16
// baseline (speedup 1.0000x reference)
#include <cuda_runtime.h>
#include <cuda_fp16.h>
#include <math.h>
#define NN 512
#define KK 50

__device__ float g_a[2*KK*NN], g_c[2*NN*KK], g_oa[2*32*NN], g_ob[2*NN*32];
__device__ float g_wos[128], g_bos[4];
__device__ __half g_s[(size_t)2*NN*NN*32];
__device__ float4 g_lg[2*NN*NN];
__device__ float4 g_geo[2*NN*NN];
__device__ int g_pref;
__device__ int g_rowf[1024];

__device__ __forceinline__ float silu(float v){return __fdividef(v,1.f+__expf(-v));}
__device__ __forceinline__ unsigned long long pk(float a,float b){
  unsigned long long r;asm("mov.b64 %0,{%1,%2};":"=l"(r):"f"(a),"f"(b));return r;}
__device__ __forceinline__ void upk(unsigned long long p,float&a,float&b){
  asm("mov.b64 {%0,%1},%2;":"=f"(a),"=f"(b):"l"(p));}
__device__ __forceinline__ void fma2(unsigned long long&d,unsigned long long a,unsigned long long b){
  asm("fma.rn.f32x2 %0,%1,%2,%0;":"+l"(d):"l"(a),"l"(b));}
__device__ __forceinline__ void lds2(unsigned a,unsigned long long&x,unsigned long long&y){
  asm("ld.shared.v2.b64 {%0,%1},[%2];":"=l"(x),"=l"(y):"r"(a));}

// k1 smem offsets (floats)
#define WSTH 2032
#define NRO (WSTH+6400)
// k2 smem offsets
#define P_CW 0
#define P_SH 4096
#define P_PT 4096
#define P_T  P_PT
#define P_HE (P_PT+512)
#define P_CS (P_PT+640)
#define P_HCI (P_PT+1024)
#define P_IN (P_PT+1152)
#define P_T1 (P_PT+1344)
#define P_T2 (P_PT+1376)
#define P_T3 (P_PT+1408)
#define P_SC (P_PT+1440)
#define P_WO2 12288
#define P_B2 13312
#define P_U  13344
#define P_RD 13360
#define P_HI 13488
#define P_GM 13520
#define P_XI 13524
#define P_VI 13528
#define SMF  13536

template<int NV>
__device__ __forceinline__ void bredN(float* v,int mx,float* sm){
  #pragma unroll
  for(int s2=16;s2;s2>>=1)
    #pragma unroll
    for(int q=0;q<NV;q++){float o=__shfl_xor_sync(~0u,v[q],s2);v[q]=mx?fmaxf(v[q],o):v[q]+o;}
  __syncthreads();
  if((threadIdx.x&31)==0)
    #pragma unroll
    for(int q=0;q<NV;q++)sm[P_RD+(threadIdx.x>>5)*NV+q]=v[q];
  __syncthreads();
  #pragma unroll
  for(int q=0;q<NV;q++){float r=sm[P_RD+q];
    #pragma unroll
    for(int w=1;w<8;w++){float o=sm[P_RD+w*NV+q];r=mx?fmaxf(r,o):r+o;}v[q]=r;}
  __syncthreads();
}
__device__ __forceinline__ void bred8sm(float* v,float* sm){
  #pragma unroll
  for(int s2=16;s2;s2>>=1){
    #pragma unroll
    for(int q=0;q<4;q++)v[q]+=__shfl_xor_sync(~0u,v[q],s2);
    #pragma unroll
    for(int q=4;q<8;q++)v[q]=fmaxf(v[q],__shfl_xor_sync(~0u,v[q],s2));
  }
  __syncthreads();
  if((threadIdx.x&31)==0)
    #pragma unroll
    for(int q=0;q<8;q++)sm[P_RD+(threadIdx.x>>5)*8+q]=v[q];
  __syncthreads();
  #pragma unroll
  for(int q=0;q<8;q++){float r=sm[P_RD+q];
    #pragma unroll
    for(int w=1;w<8;w++){float o=sm[P_RD+w*8+q];r=(q<4)?(r+o):fmaxf(r,o);}v[q]=r;}
  __syncthreads();
}
template<int NI>
__device__ __forceinline__ void gmv(const float* in,const float* __restrict__ W,
                                    const float* __restrict__ bb,float* o,int t){
  if(t<128){
    int oh=t>>2,pr=t&3;
    constexpr int CH=NI/4;
    float v=0;
    #pragma unroll
    for(int q=0;q<CH;q++)v=fmaf(in[pr*CH+q],__ldg(W+(pr*CH+q)*32+oh),v);
    v+=__shfl_xor_sync(~0u,v,1);v+=__shfl_xor_sync(~0u,v,2);
    if(pr==0)o[oh]=silu(v+__ldg(bb+oh));
  }
  __syncthreads();
}

__global__ __launch_bounds__(256,3) void mega(
  const float* __restrict__ h,const float* __restrict__ x,const float* __restrict__ v,
  const float* __restrict__ means,const float* __restrict__ betas,
  const float* __restrict__ W_in,const float* __restrict__ b_in,
  const float* __restrict__ W_o1,const float* __restrict__ b_o1,
  const float* __restrict__ W_o2,const float* __restrict__ b_o2,
  const float* __restrict__ W_sem,const float* __restrict__ b_sem,
  const float* __restrict__ W_pn1,const float* __restrict__ b_pn1,
  const float* __restrict__ W_pn2,const float* __restrict__ b_pn2,
  const float* __restrict__ W_n1,const float* __restrict__ b_n1,
  const float* __restrict__ W_n2,const float* __restrict__ b_n2,
  const float* __restrict__ W_v1,const float* __restrict__ b_v1,
  const float* __restrict__ W_v2,const float* __restrict__ W_vm,
  const float* __restrict__ log_gamma,float* __restrict__ out){
  extern __shared__ float sm[];
  const int blk=blockIdx.x,t=threadIdx.x;
  // ================= PRE =================
  if(blk<1025){
    if(blk==1024){
      if(t<128){int o=t>>2,hd=t&3;float a=0;
        for(int m=0;m<32;m++)a=fmaf(W_o2[o*32+m],W_sem[m*4+hd],a);
        g_wos[t]=a;
      }else if(t<132){int hd=t-128;float a=b_sem[hd];
        for(int m=0;m<32;m++)a=fmaf(b_o2[m],W_sem[m*4+hd],a);
        g_bos[hd]=a;}
    }else{
      int b=blk>>9,n=blk&(NN-1);
      __shared__ float hr[32];
      if(t<32)hr[t]=h[blk*32+t];
      __syncthreads();
      if(t<KK){
        float a=0,c=b_in[t];
        for(int f=0;f<32;f++){a=fmaf(hr[f],W_in[f*KK+t],a);c=fmaf(hr[f],W_in[(32+f)*KK+t],c);}
        g_a[((b*KK+t)<<9)+n]=a; g_c[blk*KK+t]=c;
      }else if(t>=64&&t<96){
        int q=t-64;float a=0;
        for(int f=0;f<32;f++)a=fmaf(hr[f],W_o1[f*32+q],a);
        g_oa[((b*32+q)<<9)+n]=a;
      }else if(t>=96&&t<128){
        int q=t-96;float a=0;
        for(int f=0;f<32;f++)a=fmaf(hr[f],W_o1[(32+f)*32+q],a);
        g_ob[(blk<<5)+q]=a;
      }
    }
    __threadfence();
    __syncthreads();
    if(t==0)atomicAdd(&g_pref,1);
    return;
  }
  // ================= PRODUCER (k1) =================
  if(blk<3073){
    float* sw=sm;
    __half* wh=(__half*)(sw+WSTH);
    const int bi=blk-1025,b=bi>>10,r=bi&1023,i=r>>1,jb=(r&1)<<8;
    const unsigned su=(unsigned)__cvta_generic_to_shared(sw);
    // weights don't depend on pre
    for(int q=t;q<1632;q+=256)sw[q]=W_o1[64*32+q];
    if(t>=192&&t<224)sw[1960+t-192]=b_o1[t-192];
    if(t==255){while(atomicAdd(&g_pref,0)<1025);}
    __syncthreads();
    __threadfence();
    if(t<KK)*(float4*)&sw[1632+t*4]=make_float4(means[t],betas[t],g_c[(b*NN+i)*KK+t],0.f);
    if(t>=64&&t<192)sw[1832+t-64]=g_wos[t-64];
    if(t>=224)sw[1992+t-224]=g_ob[((b*NN+i)<<5)+t-224];
    if(t<4)sw[2024+t]=g_bos[t];
    if(t>=4&&t<7)sw[2028+t-4]=x[(b*NN+i)*3+t-4];
    __syncthreads();
    {
      const int j=jb+t;
      size_t pidx=((size_t)(b*NN+i)<<9)+j;
      const float* xj=x+(size_t)((b<<9)+j)*3;
      float d0=xj[0]-sw[2028],d1=xj[1]-sw[2029],d2=xj[2]-sw[2030];
      float nr=sqrtf(d0*d0+d1*d1+d2*d2+1e-5f),ri=__fdividef(1.f,nr+1e-5f);
      g_geo[pidx]=make_float4(d0*ri,d1*ri,d2*ri,nr);
      float e=__expf(-nr);
      float cut=(nr<5.f)?0.5f*(__cosf(nr*0.6283185307179586f)+1.f):0.f;
      const float* ga=g_a+(((size_t)b*KK)<<9)+j;
      #pragma unroll
      for(int c=0;c<2;c++){
        float av[25];
        #pragma unroll
        for(int q=0;q<25;q++)av[q]=ga[(size_t)(c*25+q)<<9];
        #pragma unroll
        for(int q=0;q<25;q++){
          int k=c*25+q;float4 mbc=*(float4*)&sw[1632+k*4];
          float dm=e-mbc.x;
          wh[k*256+t]=__float2half_rn(cut*__expf(-mbc.y*dm*dm)*(av[q]+mbc.z));
        }
      }
      sw[NRO+t]=nr;
    }
    __syncthreads();
    const int og=t&1,jt=t>>1;
    const int j0=jb+2*jt;
    float2 nr2=*(float2*)&sw[NRO+2*jt];
    unsigned long long a0[8],a1[8];
    {
      const size_t obase=(((size_t)b*32)<<9)+j0;
      #pragma unroll
      for(int q=0;q<8;q++){
        int o0=og*16+2*q,o1=o0+1;
        float2 vA=*(const float2*)(g_oa+obase+((size_t)o0<<9));
        float2 vB=*(const float2*)(g_oa+obase+((size_t)o1<<9));
        float bA=sw[1992+o0]+sw[1960+o0],wA=sw[1600+o0];
        float bB=sw[1992+o1]+sw[1960+o1],wB=sw[1600+o1];
        a0[q]=pk(vA.x+bA+nr2.x*wA,vB.x+bB+nr2.x*wB);
        a1[q]=pk(vA.y+bA+nr2.y*wA,vB.y+bB+nr2.y*wB);
      }
    }
    {
      unsigned wbase=su+(unsigned)(og*64);
      unsigned wwa=su+(unsigned)(WSTH*4)+(unsigned)(jt*4);
      #pragma unroll 2
      for(int k=0;k<50;k++){
        unsigned wjh;
        asm("ld.shared.b32 %0,[%1];":"=r"(wjh):"r"(wwa+(unsigned)(k*512)));
        float2 wj=__half22float2(*(__half2*)&wjh);
        unsigned long long wp0=pk(wj.x,wj.x),wp1=pk(wj.y,wj.y);
        unsigned wa=wbase+(unsigned)(k*128);
        unsigned long long w01,w23,w45,w67;
        lds2(wa,w01,w23);lds2(wa+16,w45,w67);
        fma2(a0[0],wp0,w01);fma2(a0[1],wp0,w23);fma2(a0[2],wp0,w45);fma2(a0[3],wp0,w67);
        fma2(a1[0],wp1,w01);fma2(a1[1],wp1,w23);fma2(a1[2],wp1,w45);fma2(a1[3],wp1,w67);
        unsigned long long w89,wab,wcd,wef;
        lds2(wa+32,w89,wab);lds2(wa+48,wcd,wef);
        fma2(a0[4],wp0,w89);fma2(a0[5],wp0,wab);fma2(a0[6],wp0,wcd);fma2(a0[7],wp0,wef);
        fma2(a1[4],wp1,w89);fma2(a1[5],wp1,wab);fma2(a1[6],wp1,wcd);fma2(a1[7],wp1,wef);
      }
    }
    float L0[4]={0,0,0,0},L1[4]={0,0,0,0};
    unsigned hs0[8],hs1[8];
    #pragma unroll
    for(int q=0;q<8;q++){
      float sA0,sB0,sA1,sB1;
      upk(a0[q],sA0,sB0);upk(a1[q],sA1,sB1);
      sA0=silu(sA0);sB0=silu(sB0);sA1=silu(sA1);sB1=silu(sB1);
      int o0=og*16+2*q;
      float4 wv0=*(float4*)&sw[1832+o0*4];
      float4 wv1=*(float4*)&sw[1832+o0*4+4];
      L0[0]=fmaf(sA0,wv0.x,fmaf(sB0,wv1.x,L0[0]));
      L0[1]=fmaf(sA0,wv0.y,fmaf(sB0,wv1.y,L0[1]));
      L0[2]=fmaf(sA0,wv0.z,fmaf(sB0,wv1.z,L0[2]));
      L0[3]=fmaf(sA0,wv0.w,fmaf(sB0,wv1.w,L0[3]));
      L1[0]=fmaf(sA1,wv0.x,fmaf(sB1,wv1.x,L1[0]));
      L1[1]=fmaf(sA1,wv0.y,fmaf(sB1,wv1.y,L1[1]));
      L1[2]=fmaf(sA1,wv0.z,fmaf(sB1,wv1.z,L1[2]));
      L1[3]=fmaf(sA1,wv0.w,fmaf(sB1,wv1.w,L1[3]));
      __half2 h0=__floats2half2_rn(sA0,sB0);hs0[q]=*(unsigned*)&h0;
      __half2 h1=__floats2half2_rn(sA1,sB1);hs1[q]=*(unsigned*)&h1;
    }
    #pragma unroll
    for(int d=0;d<4;d++){
      L0[d]+=__shfl_xor_sync(~0u,L0[d],1);
      L1[d]+=__shfl_xor_sync(~0u,L1[d],1);
    }
    {
      size_t p0=((size_t)(b*NN+i)<<9)+j0;
      float Lw[4];
      #pragma unroll
      for(int d=0;d<4;d++){
        float vv=(og?L1[d]:L0[d])+sw[2024+d];
        Lw[d]=(vv>0.f)?vv:0.2f*vv;
      }
      g_lg[p0+og]=make_float4(Lw[0],Lw[1],Lw[2],Lw[3]);
      uint4* d0p=(uint4*)(g_s+p0*32+og*16);
      d0p[0]=make_uint4(hs0[0],hs0[1],hs0[2],hs0[3]);
      d0p[1]=make_uint4(hs0[4],hs0[5],hs0[6],hs0[7]);
      uint4* d1p=(uint4*)(g_s+(p0+1)*32+og*16);
      d1p[0]=make_uint4(hs1[0],hs1[1],hs1[2],hs1[3]);
      d1p[1]=make_uint4(hs1[4],hs1[5],hs1[6],hs1[7]);
    }
    __threadfence();
    __syncthreads();
    if(t==0)atomicAdd(&g_rowf[(b<<9)+i],1);
    return;
  }
  // ================= CONSUMER (k2) =================
  const int ci=blk-3073,b=ci>>9,i=ci&(NN-1);
  if(t==0){while(atomicAdd(&g_rowf[(b<<9)+i],0)<2);}
  __syncthreads();
  __threadfence();
  const size_t base=((size_t)(b*NN+i))<<9;
  for(int q=t;q<1024;q+=256)sm[P_WO2+q]=W_o2[q];
  if(t<32){sm[P_B2+t]=b_o2[t];sm[P_HI+t]=h[(b*NN+i)*32+t];}
  if(t>=32&&t<36)sm[P_GM+t-32]=__expf(log_gamma[t-32]);
  if(t>=36&&t<39){sm[P_XI+t-36]=x[(b*NN+i)*3+t-36];sm[P_VI+t-36]=v[(b*NN+i)*3+t-36];}
  const uint4* spp=(const uint4*)(g_s+base*32);
  for(int q=t;q<2048;q+=256)((uint4*)(sm+P_SH+((q>>2)<<4)))[q&3]=spp[q];
  int j0=t,j1=t+256;
  float4 ge0=g_geo[base+j0],ge1=g_geo[base+j1];
  *(float4*)&sm[P_CW+j0*8+4]=make_float4(ge0.x,ge0.y,ge0.z,0.f);
  *(float4*)&sm[P_CW+j1*8+4]=make_float4(ge1.x,ge1.y,ge1.z,0.f);
  float4 q0=g_lg[base+j0],q1=g_lg[base+j1];
  __syncthreads();
  float nr0=ge0.w,nr1=ge1.w;
  float mk0=(j0==i)?1e5f:0.f,mk1=(j1==i)?1e5f:0.f;
  float s0[4]={q0.x-mk0,q0.y-mk0,q0.z-mk0,q0.w-mk0};
  float s1[4]={q1.x-mk1,q1.y-mk1,q1.z-mk1,q1.w-mk1};
  float e0[4],e1[4],RM[8];
  #pragma unroll
  for(int hd=0;hd<4;hd++){float g=sm[P_GM+hd];
    e0[hd]=__expf(-(nr0+mk0)*g);e1[hd]=__expf(-(nr1+mk1)*g);
    RM[hd]=e0[hd]+e1[hd];
    RM[4+hd]=fmaxf(s0[hd],s1[hd]);
  }
  bred8sm(RM,sm);
  #pragma unroll
  for(int hd=0;hd<4;hd++){
    float iv=__fdividef(1.f,RM[hd]);e0[hd]*=iv;e1[hd]*=iv;
    s0[hd]=__expf(s0[hd]-RM[4+hd]);s1[hd]=__expf(s1[hd]-RM[4+hd]);
    RM[hd]=s0[hd]+s1[hd];
  }
  bredN<4>(RM,0,sm);
  float R[16];
  #pragma unroll
  for(int hd=0;hd<4;hd++){
    float iv=__fdividef(1.f,RM[hd]);s0[hd]*=iv;s1[hd]*=iv;
    float c0=__expf(e0[hd]*s0[hd]),c1=__expf(e1[hd]*s1[hd]);
    e0[hd]=c0;e1[hd]=c1;
    R[hd]=c0+c1;
    R[4+hd*3+0]=c0*ge0.x+c1*ge1.x;
    R[4+hd*3+1]=c0*ge0.y+c1*ge1.y;
    R[4+hd*3+2]=c0*ge0.z+c1*ge1.z;
  }
  bredN<16>(R,0,sm);
  #pragma unroll
  for(int hd=0;hd<4;hd++){float iv=__fdividef(1.f,R[hd]);e0[hd]*=iv;e1[hd]*=iv;}
  *(float4*)&sm[P_CW+j0*8]=make_float4(e0[0],e0[1],e0[2],e0[3]);
  *(float4*)&sm[P_CW+j1*8]=make_float4(e1[0],e1[1],e1[2],e1[3]);
  if(t<12){int hd=t/3,d=t%3;sm[P_U+hd*3+d]=__fdividef(R[4+hd*3+d],R[hd]);}
  __syncthreads();
  {
    int lane=t&31,slice=t>>5,og=lane>>2,hd=lane&3;
    float a[16];
    #pragma unroll
    for(int q=0;q<16;q++)a[q]=0.f;
    int jb2=slice<<6;
    #pragma unroll 4
    for(int jj=0;jj<64;jj++){
      int j=jb2+jj;
      uint2 sp=*(uint2*)&sm[P_SH+j*16+og*2];
      float2 fA=__half22float2(*(__half2*)&sp.x),fB=__half22float2(*(__half2*)&sp.y);
      float cb=sm[P_CW+j*8+hd];
      float4 un=*(float4*)&sm[P_CW+j*8+4];
      float p;
      p=fA.x*cb;a[0]+=p;a[1]=fmaf(p,un.x,a[1]);a[2]=fmaf(p,un.y,a[2]);a[3]=fmaf(p,un.z,a[3]);
      p=fA.y*cb;a[4]+=p;a[5]=fmaf(p,un.x,a[5]);a[6]=fmaf(p,un.y,a[6]);a[7]=fmaf(p,un.z,a[7]);
      p=fB.x*cb;a[8]+=p;a[9]=fmaf(p,un.x,a[9]);a[10]=fmaf(p,un.y,a[10]);a[11]=fmaf(p,un.z,a[11]);
      p=fB.y*cb;a[12]+=p;a[13]=fmaf(p,un.x,a[13]);a[14]=fmaf(p,un.y,a[14]);a[15]=fmaf(p,un.z,a[15]);
    }
    __syncthreads();
    #pragma unroll
    for(int c=0;c<4;c++){
      int ix=c*4;
      sm[P_PT+lane+32*((ix+0)*8+slice)]=a[ix+0];
      sm[P_PT+lane+32*((ix+1)*8+slice)]=a[ix+1];
      sm[P_PT+lane+32*((ix+2)*8+slice)]=a[ix+2];
      sm[P_PT+lane+32*((ix+3)*8+slice)]=a[ix+3];
    }
  }
  __syncthreads();
  float vv0=0,vv1=0;
  {
    int combo=t&31,i0=t>>5,i1=(t>>5)+8;
    #pragma unroll
    for(int s2=0;s2<8;s2++){
      vv0+=sm[P_PT+combo+32*(i0*8+s2)];
      vv1+=sm[P_PT+combo+32*(i1*8+s2)];
    }
  }
  __syncthreads();
  sm[P_T+(t&31)+32*(t>>5)]=vv0;
  sm[P_T+(t&31)+32*((t>>5)+8)]=vv1;
  __syncthreads();
  #pragma unroll
  for(int r2=0;r2<2;r2++){
    int q=t+(r2<<8),hid=q>>4,hd=(q>>2)&3,m=q&3;
    float vv=0;
    #pragma unroll 8
    for(int o=0;o<32;o++)
      vv=fmaf(sm[P_WO2+o*32+hid],sm[P_T+((o>>2)*4+hd)+32*(((o&3)<<2)+m)],vv);
    float b2=sm[P_B2+hid];int c=hid*4+hd;
    if(m==0)sm[P_HE+c]=vv+b2;
    else sm[P_CS+c*3+m-1]=(vv+b2*sm[P_U+hd*3+m-1])*(1.f/512.f);
  }
  __syncthreads();
  if(t<128){
    float a0=sm[P_CS+t*3],a1=sm[P_CS+t*3+1],a2=sm[P_CS+t*3+2];
    sm[P_HCI+t]=a0*a0+a1*a1+a2*a2;
  }
  __syncthreads();
  gmv<128>(&sm[P_HCI],W_pn1,b_pn1,&sm[P_T1],t);
  gmv<32>(&sm[P_T1],W_pn2,b_pn2,&sm[P_T2],t);
  if(t<192)sm[P_IN+t]=(t<32)?sm[P_HI+t]:(t<160)?sm[P_HE+t-32]:sm[P_T2+t-160];
  __syncthreads();
  gmv<192>(&sm[P_IN],W_n1,b_n1,&sm[P_T1],t);
  if(t<128){
    int oh=t>>2,pr=t&3;float vv=0;
    #pragma unroll
    for(int q=0;q<8;q++)vv=fmaf(sm[P_T1+pr*8+q],__ldg(W_n2+(pr*8+q)*32+oh),vv);
    vv+=__shfl_xor_sync(~0u,vv,1);vv+=__shfl_xor_sync(~0u,vv,2);
    if(pr==0){
      float hv=sm[P_HI+oh]+silu(vv+__ldg(b_n2+oh));
      sm[P_T2+oh]=hv;
      out[(b*NN+i)*32+oh]=hv;
    }
  }
  __syncthreads();
  gmv<32>(&sm[P_T2],W_v1,b_v1,&sm[P_T3],t);
  if(t<32){
    float g=sm[P_T3+t]*__ldg(W_v2+t);
    #pragma unroll
    for(int s2=16;s2;s2>>=1)g+=__shfl_xor_sync(~0u,g,s2);
    if(t==0)sm[P_SC]=g;
  }
  if(t>=32&&t<128){
    int d=(t>>5)-1,ln=t&31;float vv=0;
    #pragma unroll
    for(int r2=0;r2<4;r2++){int c=ln+(r2<<5);vv=fmaf(sm[P_CS+c*3+d],__ldg(W_vm+c),vv);}
    #pragma unroll
    for(int s2=16;s2;s2>>=1)vv+=__shfl_xor_sync(~0u,vv,s2);
    if(ln==0)sm[P_SC+1+d]=vv;
  }
  __syncthreads();
  if(t<3){
    float vn=sm[P_SC]*sm[P_VI+t]+sm[P_SC+1+t];
    out[32768+(b*NN+i)*3+t]=sm[P_XI+t]+vn;
    out[35840+(b*NN+i)*3+t]=vn;
  }
}

extern "C" void kernel_launch(void* const* d_in,const int* in_sizes,int n_in,
                              void* d_out,int out_size){
  const float *h=(const float*)d_in[0],*x=(const float*)d_in[1],*v=(const float*)d_in[2],
    *means=(const float*)d_in[3],*betas=(const float*)d_in[4],
    *W_in=(const float*)d_in[5],*b_in=(const float*)d_in[6],
    *W_o1=(const float*)d_in[7],*b_o1=(const float*)d_in[8],
    *W_o2=(const float*)d_in[9],*b_o2=(const float*)d_in[10],
    *W_sem=(const float*)d_in[11],*b_sem=(const float*)d_in[12],
    *W_pn1=(const float*)d_in[13],*b_pn1=(const float*)d_in[14],
    *W_pn2=(const float*)d_in[15],*b_pn2=(const float*)d_in[16],
    *W_n1=(const float*)d_in[17],*b_n1=(const float*)d_in[18],
    *W_n2=(const float*)d_in[19],*b_n2=(const float*)d_in[20],
    *W_v1=(const float*)d_in[21],*b_v1=(const float*)d_in[22],
    *W_v2=(const float*)d_in[23],*W_vm=(const float*)d_in[24],
    *log_gamma=(const float*)d_in[25];
  float* out=(float*)d_out;
  cudaFuncSetAttribute(mega,cudaFuncAttributeMaxDynamicSharedMemorySize,SMF*4);
  mega<<<4097,256,SMF*4>>>(h,x,v,means,betas,W_in,b_in,W_o1,b_o1,W_o2,b_o2,W_sem,b_sem,
    W_pn1,b_pn1,W_pn2,b_pn2,W_n1,b_n1,W_n2,b_n2,W_v1,b_v1,W_v2,W_vm,log_gamma,out);
}

// round 17
// speedup vs baseline: 1.0307x; 1.0307x over previous
#include <cuda_runtime.h>
#include <cuda_fp16.h>
#include <math.h>
#define NN 512
#define KK 50

__device__ float g_a[2*KK*NN], g_c[2*NN*KK], g_oa[2*32*NN], g_ob[2*NN*32];
__device__ float g_wos[128], g_bos[4];
__device__ __half g_s[(size_t)2*NN*NN*32];
__device__ float4 g_lg[2*NN*NN];
__device__ float4 g_geo[2*NN*NN];

__device__ __forceinline__ float silu(float v){return __fdividef(v,1.f+__expf(-v));}
__device__ __forceinline__ unsigned long long pk(float a,float b){
  unsigned long long r;asm("mov.b64 %0,{%1,%2};":"=l"(r):"f"(a),"f"(b));return r;}
__device__ __forceinline__ void upk(unsigned long long p,float&a,float&b){
  asm("mov.b64 {%0,%1},%2;":"=f"(a),"=f"(b):"l"(p));}
__device__ __forceinline__ void fma2(unsigned long long&d,unsigned long long a,unsigned long long b){
  asm("fma.rn.f32x2 %0,%1,%2,%0;":"+l"(d):"l"(a),"l"(b));}
__device__ __forceinline__ void lds2(unsigned a,unsigned long long&x,unsigned long long&y){
  asm("ld.shared.v2.b64 {%0,%1},[%2];":"=l"(x),"=l"(y):"r"(a));}

__global__ void pre_node(const float* __restrict__ h,const float* __restrict__ W_in,
                         const float* __restrict__ b_in,const float* __restrict__ W_o1,
                         const float* __restrict__ W_o2,const float* __restrict__ W_sem,
                         const float* __restrict__ b_o2,const float* __restrict__ b_sem){
  int bn=blockIdx.x,t=threadIdx.x;
  if(bn==1024){
    if(t<128){int o=t>>2,hd=t&3;float a=0;
      for(int m=0;m<32;m++)a=fmaf(W_o2[o*32+m],W_sem[m*4+hd],a);
      g_wos[t]=a;
    }else if(t<132){int hd=t-128;float a=b_sem[hd];
      for(int m=0;m<32;m++)a=fmaf(b_o2[m],W_sem[m*4+hd],a);
      g_bos[hd]=a;}
    return;
  }
  int b=bn>>9,n=bn&(NN-1);
  __shared__ float hr[32];
  if(t<32)hr[t]=h[bn*32+t];
  __syncthreads();
  if(t<KK){
    float a=0,c=b_in[t];
    for(int f=0;f<32;f++){a=fmaf(hr[f],W_in[f*KK+t],a);c=fmaf(hr[f],W_in[(32+f)*KK+t],c);}
    g_a[((b*KK+t)<<9)+n]=a; g_c[bn*KK+t]=c;
  }else if(t>=64&&t<96){
    int q=t-64;float a=0;
    for(int f=0;f<32;f++)a=fmaf(hr[f],W_o1[f*32+q],a);
    g_oa[((b*32+q)<<9)+n]=a;
  }else if(t>=96&&t<128){
    int q=t-96;float a=0;
    for(int f=0;f<32;f++)a=fmaf(hr[f],W_o1[(32+f)*32+q],a);
    g_ob[(bn<<5)+q]=a;
  }
}

#define WSTH 2032
#define NRO (WSTH+6400)
#define SMF1 (NRO+256)
__global__ __launch_bounds__(256,3) void k1(
  const float* __restrict__ x,const float* __restrict__ means,const float* __restrict__ betas,
  const float* __restrict__ W_o1,const float* __restrict__ b_o1){
  extern __shared__ float sw[];
  __half* wh=(__half*)(sw+WSTH);
  const int bi=blockIdx.x,b=bi>>10,r=bi&1023,i=r>>1,jb=(r&1)<<8,t=threadIdx.x;
  const unsigned su=(unsigned)__cvta_generic_to_shared(sw);
  // --- hoisted L2 loads: ga row (50), xj — overlap with smem fills below
  const int j=jb+t;
  float av[50];
  {
    const float* ga=g_a+(((size_t)b*KK)<<9)+j;
    #pragma unroll
    for(int q=0;q<25;q++)av[q]=ga[(size_t)q<<9];
    #pragma unroll
    for(int q=25;q<50;q++)av[q]=ga[(size_t)q<<9];
  }
  const float* xj=x+(size_t)((b<<9)+j)*3;
  float xd0=xj[0],xd1=xj[1],xd2=xj[2];
  for(int q=t;q<1632;q+=256)sw[q]=W_o1[64*32+q];
  if(t<KK)*(float4*)&sw[1632+t*4]=make_float4(means[t],betas[t],g_c[(b*NN+i)*KK+t],0.f);
  if(t>=64&&t<192)sw[1832+t-64]=g_wos[t-64];
  if(t>=192&&t<224)sw[1960+t-192]=b_o1[t-192];
  if(t>=224)sw[1992+t-224]=g_ob[((b*NN+i)<<5)+t-224];
  if(t<4)sw[2024+t]=g_bos[t];
  if(t>=4&&t<7)sw[2028+t-4]=x[(b*NN+i)*3+t-4];
  __syncthreads();
  // --- staging: thread t -> j : geometry + w[k][t] (fp16)
  {
    size_t pidx=((size_t)(b*NN+i)<<9)+j;
    float d0=xd0-sw[2028],d1=xd1-sw[2029],d2=xd2-sw[2030];
    float nr=sqrtf(d0*d0+d1*d1+d2*d2+1e-5f),ri=__fdividef(1.f,nr+1e-5f);
    g_geo[pidx]=make_float4(d0*ri,d1*ri,d2*ri,nr);
    float e=__expf(-nr);
    float cut=(nr<5.f)?0.5f*(__cosf(nr*0.6283185307179586f)+1.f):0.f;
    #pragma unroll
    for(int k=0;k<50;k++){
      float4 mbc=*(float4*)&sw[1632+k*4];
      float dm=e-mbc.x;
      wh[k*256+t]=__float2half_rn(cut*__expf(-mbc.y*dm*dm)*(av[k]+mbc.z));
    }
    sw[NRO+t]=nr;
  }
  __syncthreads();
  const int og=t&1,jt=t>>1;
  const int j0=jb+2*jt;
  float2 nr2=*(float2*)&sw[NRO+2*jt];
  unsigned long long a0[8],a1[8];
  {
    const size_t obase=(((size_t)b*32)<<9)+j0;
    #pragma unroll
    for(int q=0;q<8;q++){
      int o0=og*16+2*q,o1=o0+1;
      float2 vA=*(const float2*)(g_oa+obase+((size_t)o0<<9));
      float2 vB=*(const float2*)(g_oa+obase+((size_t)o1<<9));
      float bA=sw[1992+o0]+sw[1960+o0],wA=sw[1600+o0];
      float bB=sw[1992+o1]+sw[1960+o1],wB=sw[1600+o1];
      a0[q]=pk(vA.x+bA+nr2.x*wA,vB.x+bB+nr2.x*wB);
      a1[q]=pk(vA.y+bA+nr2.y*wA,vB.y+bB+nr2.y*wB);
    }
  }
  {
    unsigned wbase=su+(unsigned)(og*64);
    unsigned wwa=su+(unsigned)(WSTH*4)+(unsigned)(jt*4);
    #pragma unroll 2
    for(int k=0;k<50;k++){
      unsigned wjh;
      asm("ld.shared.b32 %0,[%1];":"=r"(wjh):"r"(wwa+(unsigned)(k*512)));
      float2 wj=__half22float2(*(__half2*)&wjh);
      unsigned long long wp0=pk(wj.x,wj.x),wp1=pk(wj.y,wj.y);
      unsigned wa=wbase+(unsigned)(k*128);
      unsigned long long w01,w23,w45,w67;
      lds2(wa,w01,w23);lds2(wa+16,w45,w67);
      fma2(a0[0],wp0,w01);fma2(a0[1],wp0,w23);fma2(a0[2],wp0,w45);fma2(a0[3],wp0,w67);
      fma2(a1[0],wp1,w01);fma2(a1[1],wp1,w23);fma2(a1[2],wp1,w45);fma2(a1[3],wp1,w67);
      unsigned long long w89,wab,wcd,wef;
      lds2(wa+32,w89,wab);lds2(wa+48,wcd,wef);
      fma2(a0[4],wp0,w89);fma2(a0[5],wp0,wab);fma2(a0[6],wp0,wcd);fma2(a0[7],wp0,wef);
      fma2(a1[4],wp1,w89);fma2(a1[5],wp1,wab);fma2(a1[6],wp1,wcd);fma2(a1[7],wp1,wef);
    }
  }
  float L0[4]={0,0,0,0},L1[4]={0,0,0,0};
  unsigned hs0[8],hs1[8];
  #pragma unroll
  for(int q=0;q<8;q++){
    float sA0,sB0,sA1,sB1;
    upk(a0[q],sA0,sB0);upk(a1[q],sA1,sB1);
    sA0=silu(sA0);sB0=silu(sB0);sA1=silu(sA1);sB1=silu(sB1);
    int o0=og*16+2*q;
    float4 wv0=*(float4*)&sw[1832+o0*4];
    float4 wv1=*(float4*)&sw[1832+o0*4+4];
    L0[0]=fmaf(sA0,wv0.x,fmaf(sB0,wv1.x,L0[0]));
    L0[1]=fmaf(sA0,wv0.y,fmaf(sB0,wv1.y,L0[1]));
    L0[2]=fmaf(sA0,wv0.z,fmaf(sB0,wv1.z,L0[2]));
    L0[3]=fmaf(sA0,wv0.w,fmaf(sB0,wv1.w,L0[3]));
    L1[0]=fmaf(sA1,wv0.x,fmaf(sB1,wv1.x,L1[0]));
    L1[1]=fmaf(sA1,wv0.y,fmaf(sB1,wv1.y,L1[1]));
    L1[2]=fmaf(sA1,wv0.z,fmaf(sB1,wv1.z,L1[2]));
    L1[3]=fmaf(sA1,wv0.w,fmaf(sB1,wv1.w,L1[3]));
    __half2 h0=__floats2half2_rn(sA0,sB0);hs0[q]=*(unsigned*)&h0;
    __half2 h1=__floats2half2_rn(sA1,sB1);hs1[q]=*(unsigned*)&h1;
  }
  #pragma unroll
  for(int d=0;d<4;d++){
    L0[d]+=__shfl_xor_sync(~0u,L0[d],1);
    L1[d]+=__shfl_xor_sync(~0u,L1[d],1);
  }
  {
    size_t p0=((size_t)(b*NN+i)<<9)+j0;
    float Lw[4];
    #pragma unroll
    for(int d=0;d<4;d++){
      float vv=(og?L1[d]:L0[d])+sw[2024+d];
      Lw[d]=(vv>0.f)?vv:0.2f*vv;
    }
    g_lg[p0+og]=make_float4(Lw[0],Lw[1],Lw[2],Lw[3]);
    uint4* d0p=(uint4*)(g_s+p0*32+og*16);
    d0p[0]=make_uint4(hs0[0],hs0[1],hs0[2],hs0[3]);
    d0p[1]=make_uint4(hs0[4],hs0[5],hs0[6],hs0[7]);
    uint4* d1p=(uint4*)(g_s+(p0+1)*32+og*16);
    d1p[0]=make_uint4(hs1[0],hs1[1],hs1[2],hs1[3]);
    d1p[1]=make_uint4(hs1[4],hs1[5],hs1[6],hs1[7]);
  }
}

#define P_CW 0
#define P_SH 4096
#define P_PT 4096
#define P_T  P_PT
#define P_HE (P_PT+512)
#define P_CS (P_PT+640)
#define P_HCI (P_PT+1024)
#define P_IN (P_PT+1152)
#define P_T1 (P_PT+1344)
#define P_T2 (P_PT+1376)
#define P_T3 (P_PT+1408)
#define P_SC (P_PT+1440)
#define P_WO2 12288
#define P_B2 13312
#define P_U  13344
#define P_RD 13360
#define P_HI 13488
#define P_GM 13520
#define P_XI 13524
#define P_VI 13528
#define SMF2 13536

template<int NV>
__device__ __forceinline__ void bredN(float* v,int mx,float* sm){
  #pragma unroll
  for(int s2=16;s2;s2>>=1)
    #pragma unroll
    for(int q=0;q<NV;q++){float o=__shfl_xor_sync(~0u,v[q],s2);v[q]=mx?fmaxf(v[q],o):v[q]+o;}
  __syncthreads();
  if((threadIdx.x&31)==0)
    #pragma unroll
    for(int q=0;q<NV;q++)sm[P_RD+(threadIdx.x>>5)*NV+q]=v[q];
  __syncthreads();
  #pragma unroll
  for(int q=0;q<NV;q++){float r=sm[P_RD+q];
    #pragma unroll
    for(int w=1;w<8;w++){float o=sm[P_RD+w*NV+q];r=mx?fmaxf(r,o):r+o;}v[q]=r;}
  __syncthreads();
}
__device__ __forceinline__ void bred8sm(float* v,float* sm){
  #pragma unroll
  for(int s2=16;s2;s2>>=1){
    #pragma unroll
    for(int q=0;q<4;q++)v[q]+=__shfl_xor_sync(~0u,v[q],s2);
    #pragma unroll
    for(int q=4;q<8;q++)v[q]=fmaxf(v[q],__shfl_xor_sync(~0u,v[q],s2));
  }
  __syncthreads();
  if((threadIdx.x&31)==0)
    #pragma unroll
    for(int q=0;q<8;q++)sm[P_RD+(threadIdx.x>>5)*8+q]=v[q];
  __syncthreads();
  #pragma unroll
  for(int q=0;q<8;q++){float r=sm[P_RD+q];
    #pragma unroll
    for(int w=1;w<8;w++){float o=sm[P_RD+w*8+q];r=(q<4)?(r+o):fmaxf(r,o);}v[q]=r;}
  __syncthreads();
}
template<int NI>
__device__ __forceinline__ void gmv(const float* in,const float* __restrict__ W,
                                    const float* __restrict__ bb,float* o,int t){
  if(t<128){
    int oh=t>>2,pr=t&3;
    constexpr int CH=NI/4;
    float v=0;
    #pragma unroll
    for(int q=0;q<CH;q++)v=fmaf(in[pr*CH+q],__ldg(W+(pr*CH+q)*32+oh),v);
    v+=__shfl_xor_sync(~0u,v,1);v+=__shfl_xor_sync(~0u,v,2);
    if(pr==0)o[oh]=silu(v+__ldg(bb+oh));
  }
  __syncthreads();
}

__global__ __launch_bounds__(256,4) void k2(
  const float* __restrict__ h,const float* __restrict__ x,const float* __restrict__ v,
  const float* __restrict__ W_o2,const float* __restrict__ b_o2,
  const float* __restrict__ W_pn1,const float* __restrict__ b_pn1,
  const float* __restrict__ W_pn2,const float* __restrict__ b_pn2,
  const float* __restrict__ W_n1,const float* __restrict__ b_n1,
  const float* __restrict__ W_n2,const float* __restrict__ b_n2,
  const float* __restrict__ W_v1,const float* __restrict__ b_v1,
  const float* __restrict__ W_v2,const float* __restrict__ W_vm,
  const float* __restrict__ log_gamma,float* __restrict__ out){
  extern __shared__ float sm[];
  const int b=blockIdx.x>>9,i=blockIdx.x&(NN-1),t=threadIdx.x;
  const size_t base=((size_t)(b*NN+i))<<9;
  // hoisted per-row L2 loads (latency hides under fills below)
  int j0=t,j1=t+256;
  float4 ge0=g_geo[base+j0],ge1=g_geo[base+j1];
  float4 q0=g_lg[base+j0],q1=g_lg[base+j1];
  for(int q=t;q<1024;q+=256)sm[P_WO2+q]=W_o2[q];
  if(t<32){sm[P_B2+t]=b_o2[t];sm[P_HI+t]=h[(b*NN+i)*32+t];}
  if(t>=32&&t<36)sm[P_GM+t-32]=__expf(log_gamma[t-32]);
  if(t>=36&&t<39){sm[P_XI+t-36]=x[(b*NN+i)*3+t-36];sm[P_VI+t-36]=v[(b*NN+i)*3+t-36];}
  const uint4* spp=(const uint4*)(g_s+base*32);
  for(int q=t;q<2048;q+=256)((uint4*)(sm+P_SH+((q>>2)<<4)))[q&3]=spp[q];
  *(float4*)&sm[P_CW+j0*8+4]=make_float4(ge0.x,ge0.y,ge0.z,0.f);
  *(float4*)&sm[P_CW+j1*8+4]=make_float4(ge1.x,ge1.y,ge1.z,0.f);
  __syncthreads();
  float nr0=ge0.w,nr1=ge1.w;
  float mk0=(j0==i)?1e5f:0.f,mk1=(j1==i)?1e5f:0.f;
  float s0[4]={q0.x-mk0,q0.y-mk0,q0.z-mk0,q0.w-mk0};
  float s1[4]={q1.x-mk1,q1.y-mk1,q1.z-mk1,q1.w-mk1};
  float e0[4],e1[4],RM[8];
  #pragma unroll
  for(int hd=0;hd<4;hd++){float g=sm[P_GM+hd];
    e0[hd]=__expf(-(nr0+mk0)*g);e1[hd]=__expf(-(nr1+mk1)*g);
    RM[hd]=e0[hd]+e1[hd];
    RM[4+hd]=fmaxf(s0[hd],s1[hd]);
  }
  bred8sm(RM,sm);
  #pragma unroll
  for(int hd=0;hd<4;hd++){
    float iv=__fdividef(1.f,RM[hd]);e0[hd]*=iv;e1[hd]*=iv;
    s0[hd]=__expf(s0[hd]-RM[4+hd]);s1[hd]=__expf(s1[hd]-RM[4+hd]);
    RM[hd]=s0[hd]+s1[hd];
  }
  bredN<4>(RM,0,sm);
  float R[16];
  #pragma unroll
  for(int hd=0;hd<4;hd++){
    float iv=__fdividef(1.f,RM[hd]);s0[hd]*=iv;s1[hd]*=iv;
    float c0=__expf(e0[hd]*s0[hd]),c1=__expf(e1[hd]*s1[hd]);
    e0[hd]=c0;e1[hd]=c1;
    R[hd]=c0+c1;
    R[4+hd*3+0]=c0*ge0.x+c1*ge1.x;
    R[4+hd*3+1]=c0*ge0.y+c1*ge1.y;
    R[4+hd*3+2]=c0*ge0.z+c1*ge1.z;
  }
  bredN<16>(R,0,sm);
  #pragma unroll
  for(int hd=0;hd<4;hd++){float iv=__fdividef(1.f,R[hd]);e0[hd]*=iv;e1[hd]*=iv;}
  *(float4*)&sm[P_CW+j0*8]=make_float4(e0[0],e0[1],e0[2],e0[3]);
  *(float4*)&sm[P_CW+j1*8]=make_float4(e1[0],e1[1],e1[2],e1[3]);
  if(t<12){int hd=t/3,d=t%3;sm[P_U+hd*3+d]=__fdividef(R[4+hd*3+d],R[hd]);}
  __syncthreads();
  {
    int lane=t&31,slice=t>>5,og=lane>>2,hd=lane&3;
    float a[16];
    #pragma unroll
    for(int q=0;q<16;q++)a[q]=0.f;
    int jb2=slice<<6;
    #pragma unroll 4
    for(int jj=0;jj<64;jj++){
      int j=jb2+jj;
      uint2 sp=*(uint2*)&sm[P_SH+j*16+og*2];
      float2 fA=__half22float2(*(__half2*)&sp.x),fB=__half22float2(*(__half2*)&sp.y);
      float cb=sm[P_CW+j*8+hd];
      float4 un=*(float4*)&sm[P_CW+j*8+4];
      float p;
      p=fA.x*cb;a[0]+=p;a[1]=fmaf(p,un.x,a[1]);a[2]=fmaf(p,un.y,a[2]);a[3]=fmaf(p,un.z,a[3]);
      p=fA.y*cb;a[4]+=p;a[5]=fmaf(p,un.x,a[5]);a[6]=fmaf(p,un.y,a[6]);a[7]=fmaf(p,un.z,a[7]);
      p=fB.x*cb;a[8]+=p;a[9]=fmaf(p,un.x,a[9]);a[10]=fmaf(p,un.y,a[10]);a[11]=fmaf(p,un.z,a[11]);
      p=fB.y*cb;a[12]+=p;a[13]=fmaf(p,un.x,a[13]);a[14]=fmaf(p,un.y,a[14]);a[15]=fmaf(p,un.z,a[15]);
    }
    __syncthreads();
    #pragma unroll
    for(int c=0;c<4;c++){
      int ix=c*4;
      sm[P_PT+lane+32*((ix+0)*8+slice)]=a[ix+0];
      sm[P_PT+lane+32*((ix+1)*8+slice)]=a[ix+1];
      sm[P_PT+lane+32*((ix+2)*8+slice)]=a[ix+2];
      sm[P_PT+lane+32*((ix+3)*8+slice)]=a[ix+3];
    }
  }
  __syncthreads();
  float vv0=0,vv1=0;
  {
    int combo=t&31,i0=t>>5,i1=(t>>5)+8;
    #pragma unroll
    for(int s2=0;s2<8;s2++){
      vv0+=sm[P_PT+combo+32*(i0*8+s2)];
      vv1+=sm[P_PT+combo+32*(i1*8+s2)];
    }
  }
  __syncthreads();
  sm[P_T+(t&31)+32*(t>>5)]=vv0;
  sm[P_T+(t&31)+32*((t>>5)+8)]=vv1;
  __syncthreads();
  #pragma unroll
  for(int r2=0;r2<2;r2++){
    int q=t+(r2<<8),hid=q>>4,hd=(q>>2)&3,m=q&3;
    float vv=0;
    #pragma unroll 8
    for(int o=0;o<32;o++)
      vv=fmaf(sm[P_WO2+o*32+hid],sm[P_T+((o>>2)*4+hd)+32*(((o&3)<<2)+m)],vv);
    float b2=sm[P_B2+hid];int c=hid*4+hd;
    if(m==0)sm[P_HE+c]=vv+b2;
    else sm[P_CS+c*3+m-1]=(vv+b2*sm[P_U+hd*3+m-1])*(1.f/512.f);
  }
  __syncthreads();
  if(t<128){
    float a0=sm[P_CS+t*3],a1=sm[P_CS+t*3+1],a2=sm[P_CS+t*3+2];
    sm[P_HCI+t]=a0*a0+a1*a1+a2*a2;
  }
  __syncthreads();
  gmv<128>(&sm[P_HCI],W_pn1,b_pn1,&sm[P_T1],t);
  gmv<32>(&sm[P_T1],W_pn2,b_pn2,&sm[P_T2],t);
  if(t<192)sm[P_IN+t]=(t<32)?sm[P_HI+t]:(t<160)?sm[P_HE+t-32]:sm[P_T2+t-160];
  __syncthreads();
  gmv<192>(&sm[P_IN],W_n1,b_n1,&sm[P_T1],t);
  if(t<128){
    int oh=t>>2,pr=t&3;float vv=0;
    #pragma unroll
    for(int q=0;q<8;q++)vv=fmaf(sm[P_T1+pr*8+q],__ldg(W_n2+(pr*8+q)*32+oh),vv);
    vv+=__shfl_xor_sync(~0u,vv,1);vv+=__shfl_xor_sync(~0u,vv,2);
    if(pr==0){
      float hv=sm[P_HI+oh]+silu(vv+__ldg(b_n2+oh));
      sm[P_T2+oh]=hv;
      out[(b*NN+i)*32+oh]=hv;
    }
  }
  __syncthreads();
  gmv<32>(&sm[P_T2],W_v1,b_v1,&sm[P_T3],t);
  if(t<32){
    float g=sm[P_T3+t]*__ldg(W_v2+t);
    #pragma unroll
    for(int s2=16;s2;s2>>=1)g+=__shfl_xor_sync(~0u,g,s2);
    if(t==0)sm[P_SC]=g;
  }
  if(t>=32&&t<128){
    int d=(t>>5)-1,ln=t&31;float vv=0;
    #pragma unroll
    for(int r2=0;r2<4;r2++){int c=ln+(r2<<5);vv=fmaf(sm[P_CS+c*3+d],__ldg(W_vm+c),vv);}
    #pragma unroll
    for(int s2=16;s2;s2>>=1)vv+=__shfl_xor_sync(~0u,vv,s2);
    if(ln==0)sm[P_SC+1+d]=vv;
  }
  __syncthreads();
  if(t<3){
    float vn=sm[P_SC]*sm[P_VI+t]+sm[P_SC+1+t];
    out[32768+(b*NN+i)*3+t]=sm[P_XI+t]+vn;
    out[35840+(b*NN+i)*3+t]=vn;
  }
}

extern "C" void kernel_launch(void* const* d_in,const int* in_sizes,int n_in,
                              void* d_out,int out_size){
  const float *h=(const float*)d_in[0],*x=(const float*)d_in[1],*v=(const float*)d_in[2],
    *means=(const float*)d_in[3],*betas=(const float*)d_in[4],
    *W_in=(const float*)d_in[5],*b_in=(const float*)d_in[6],
    *W_o1=(const float*)d_in[7],*b_o1=(const float*)d_in[8],
    *W_o2=(const float*)d_in[9],*b_o2=(const float*)d_in[10],
    *W_sem=(const float*)d_in[11],*b_sem=(const float*)d_in[12],
    *W_pn1=(const float*)d_in[13],*b_pn1=(const float*)d_in[14],
    *W_pn2=(const float*)d_in[15],*b_pn2=(const float*)d_in[16],
    *W_n1=(const float*)d_in[17],*b_n1=(const float*)d_in[18],
    *W_n2=(const float*)d_in[19],*b_n2=(const float*)d_in[20],
    *W_v1=(const float*)d_in[21],*b_v1=(const float*)d_in[22],
    *W_v2=(const float*)d_in[23],*W_vm=(const float*)d_in[24],
    *log_gamma=(const float*)d_in[25];
  float* out=(float*)d_out;
  cudaFuncSetAttribute(k1,cudaFuncAttributeMaxDynamicSharedMemorySize,SMF1*4);
  cudaFuncSetAttribute(k2,cudaFuncAttributeMaxDynamicSharedMemorySize,SMF2*4);
  pre_node<<<1025,132>>>(h,W_in,b_in,W_o1,W_o2,W_sem,b_o2,b_sem);
  k1<<<2048,256,SMF1*4>>>(x,means,betas,W_o1,b_o1);
  k2<<<1024,256,SMF2*4>>>(h,x,v,W_o2,b_o2,W_pn1,b_pn1,W_pn2,b_pn2,
    W_n1,b_n1,W_n2,b_n2,W_v1,b_v1,W_v2,W_vm,log_gamma,out);
}